// round 2
// baseline (speedup 1.0000x reference)
#include <cuda_runtime.h>
#include <cuda_bf16.h>
#include <cstdint>

// Problem constants
#define BB 2
#define NN 2048
#define DD 1024
#define HH 16
#define HKV 4
#define HD 64
#define REP 4
#define MROWS (BB * NN)   // 4096

// ---------------------------------------------------------------------------
// Scratch (static device globals — allocation-free per harness rules)
// ---------------------------------------------------------------------------
__device__ float g_q[MROWS * DD];        // (B*N, H*HD)   16 MB
__device__ float g_k[MROWS * HKV * HD];  // (B*N, HKV*HD)  4 MB
__device__ float g_v[MROWS * HKV * HD];  //                4 MB
__device__ float g_o[MROWS * DD];        // attention out 16 MB

// ---------------------------------------------------------------------------
// SGEMM: C[M,N] = A[M,K] @ B[K,N], all row-major. 128x128x8 tile, 256 thr,
// 8x8 per-thread microtile. M,N multiples of 128; K multiple of 8.
// ---------------------------------------------------------------------------
#define GBM 128
#define GBN 128
#define GBK 8
#define GTM 8
#define GTN 8

__global__ __launch_bounds__(256) void sgemm128(
    int M, int N, int K,
    const float* __restrict__ A, const float* __restrict__ B,
    float* __restrict__ C)
{
    __shared__ float As[GBK][GBM];
    __shared__ float Bs[GBK][GBN];

    const int tid  = threadIdx.x;
    const int brow = blockIdx.y;
    const int bcol = blockIdx.x;

    const int tcol = tid % (GBN / GTN);  // 0..15
    const int trow = tid / (GBN / GTN);  // 0..15

    float acc[GTM][GTN];
#pragma unroll
    for (int i = 0; i < GTM; i++)
#pragma unroll
        for (int j = 0; j < GTN; j++) acc[i][j] = 0.f;

    // A tile loads: 128 rows x 8 cols = 256 float4 (2 per row)
    const int aRow  = tid >> 1;          // 0..127
    const int aCol4 = (tid & 1) * 4;     // 0 or 4
    // B tile loads: 8 rows x 128 cols = 256 float4 (32 per row)
    const int bRow  = tid >> 5;          // 0..7
    const int bCol4 = (tid & 31) * 4;

    const float* Ab = A + (size_t)(brow * GBM) * K;
    const float* Bb = B + bcol * GBN;

    for (int k0 = 0; k0 < K; k0 += GBK) {
        float4 a4 = *(const float4*)(Ab + (size_t)aRow * K + k0 + aCol4);
        As[aCol4 + 0][aRow] = a4.x;
        As[aCol4 + 1][aRow] = a4.y;
        As[aCol4 + 2][aRow] = a4.z;
        As[aCol4 + 3][aRow] = a4.w;
        float4 b4 = *(const float4*)(Bb + (size_t)(k0 + bRow) * N + bCol4);
        *(float4*)&Bs[bRow][bCol4] = b4;
        __syncthreads();

        float regM[GTM], regN[GTN];
#pragma unroll
        for (int k = 0; k < GBK; k++) {
#pragma unroll
            for (int i = 0; i < GTM; i++) regM[i] = As[k][trow * GTM + i];
#pragma unroll
            for (int j = 0; j < GTN; j++) regN[j] = Bs[k][tcol * GTN + j];
#pragma unroll
            for (int i = 0; i < GTM; i++)
#pragma unroll
                for (int j = 0; j < GTN; j++)
                    acc[i][j] = fmaf(regM[i], regN[j], acc[i][j]);
        }
        __syncthreads();
    }

    float* Cb = C + (size_t)(brow * GBM + trow * GTM) * N + bcol * GBN + tcol * GTN;
#pragma unroll
    for (int i = 0; i < GTM; i++) {
        *(float4*)(Cb + (size_t)i * N + 0) =
            make_float4(acc[i][0], acc[i][1], acc[i][2], acc[i][3]);
        *(float4*)(Cb + (size_t)i * N + 4) =
            make_float4(acc[i][4], acc[i][5], acc[i][6], acc[i][7]);
    }
}

// ---------------------------------------------------------------------------
// Flash-style attention, fp32. 128 query rows/block, one row per thread.
// K/V tiles of 64 rows staged in shared memory. Online softmax (exp2 domain).
// All smem reads are explicit float4 (LDS.128) to keep issue slots for FFMA.
// Q layout: (B*N, H*HD); K/V layout: (B*N, HKV*HD); O layout: (B*N, H*HD).
// ---------------------------------------------------------------------------
#define ABR 128   // query rows per block
#define ATC 64    // kv rows per tile

__global__ __launch_bounds__(128) void attn_kernel(
    const float* __restrict__ Q, const float* __restrict__ K,
    const float* __restrict__ V, float* __restrict__ O)
{
    __shared__ float Ks[ATC][HD];
    __shared__ float Vs[ATC][HD];

    const int tid = threadIdx.x;
    const int b   = blockIdx.z;
    const int h   = blockIdx.y;
    const int n   = blockIdx.x * ABR + tid;
    const int kvh = h / REP;

    // fold 1/sqrt(HD) and log2(e) into q so we can use exp2f
    const float scale = 0.125f * 1.4426950408889634f;

    float4 q[HD / 4];
    {
        const float4* qp = (const float4*)(Q + ((size_t)(b * NN + n)) * DD + h * HD);
#pragma unroll
        for (int d = 0; d < HD / 4; d++) {
            float4 t = qp[d];
            q[d] = make_float4(t.x * scale, t.y * scale, t.z * scale, t.w * scale);
        }
    }

    float4 acc[HD / 4];
#pragma unroll
    for (int d = 0; d < HD / 4; d++) acc[d] = make_float4(0.f, 0.f, 0.f, 0.f);
    float m = -1e30f, l = 0.f;

    for (int t0 = 0; t0 < NN; t0 += ATC) {
        __syncthreads();
        // cooperative K/V tile load: 64 rows x 16 float4 per tile
        for (int i = tid; i < ATC * (HD / 4); i += ABR) {
            int r  = i >> 4;
            int c4 = (i & 15) * 4;
            size_t base = ((size_t)(b * NN + t0 + r)) * (HKV * HD) + kvh * HD + c4;
            *(float4*)&Ks[r][c4] = *(const float4*)(K + base);
            *(float4*)&Vs[r][c4] = *(const float4*)(V + base);
        }
        __syncthreads();

#pragma unroll 1
        for (int j0 = 0; j0 < ATC; j0 += 16) {
            float s[16];
#pragma unroll
            for (int jj = 0; jj < 16; jj++) s[jj] = 0.f;
#pragma unroll
            for (int d = 0; d < HD / 4; d++) {
                const float4 qd = q[d];
#pragma unroll
                for (int jj = 0; jj < 16; jj++) {
                    const float4 k4 = *(const float4*)&Ks[j0 + jj][d * 4];
                    s[jj] = fmaf(qd.x, k4.x,
                            fmaf(qd.y, k4.y,
                            fmaf(qd.z, k4.z,
                            fmaf(qd.w, k4.w, s[jj]))));
                }
            }
            float cm = m;
#pragma unroll
            for (int jj = 0; jj < 16; jj++) cm = fmaxf(cm, s[jj]);
            const float cf = exp2f(m - cm);
            m = cm;
            l *= cf;
#pragma unroll
            for (int d = 0; d < HD / 4; d++) {
                acc[d].x *= cf; acc[d].y *= cf; acc[d].z *= cf; acc[d].w *= cf;
            }
            float p[16];
#pragma unroll
            for (int jj = 0; jj < 16; jj++) {
                p[jj] = exp2f(s[jj] - m);
                l += p[jj];
            }
#pragma unroll
            for (int jj = 0; jj < 16; jj++) {
                const float pj = p[jj];
#pragma unroll
                for (int d = 0; d < HD / 4; d++) {
                    const float4 v4 = *(const float4*)&Vs[j0 + jj][d * 4];
                    acc[d].x = fmaf(pj, v4.x, acc[d].x);
                    acc[d].y = fmaf(pj, v4.y, acc[d].y);
                    acc[d].z = fmaf(pj, v4.z, acc[d].z);
                    acc[d].w = fmaf(pj, v4.w, acc[d].w);
                }
            }
        }
    }

    const float inv = 1.f / l;
    float4* op = (float4*)(O + ((size_t)(b * NN + n)) * DD + h * HD);
#pragma unroll
    for (int d = 0; d < HD / 4; d++) {
        op[d] = make_float4(acc[d].x * inv, acc[d].y * inv,
                            acc[d].z * inv, acc[d].w * inv);
    }
}

// ---------------------------------------------------------------------------
// Launch
// ---------------------------------------------------------------------------
extern "C" void kernel_launch(void* const* d_in, const int* in_sizes, int n_in,
                              void* d_out, int out_size)
{
    const float* x  = (const float*)d_in[0];
    const float* Wq = (const float*)d_in[1];
    const float* Wk = (const float*)d_in[2];
    const float* Wv = (const float*)d_in[3];
    const float* Wo = (const float*)d_in[4];
    float* out = (float*)d_out;

    float *q, *k, *v, *o;
    cudaGetSymbolAddress((void**)&q, g_q);
    cudaGetSymbolAddress((void**)&k, g_k);
    cudaGetSymbolAddress((void**)&v, g_v);
    cudaGetSymbolAddress((void**)&o, g_o);

    // Q = x @ Wq : (4096,1024) x (1024,1024)
    sgemm128<<<dim3(DD / GBN, MROWS / GBM), 256>>>(MROWS, DD, DD, x, Wq, q);
    // K = x @ Wk : (4096,1024) x (1024,256)
    sgemm128<<<dim3((HKV * HD) / GBN, MROWS / GBM), 256>>>(MROWS, HKV * HD, DD, x, Wk, k);
    // V = x @ Wv
    sgemm128<<<dim3((HKV * HD) / GBN, MROWS / GBM), 256>>>(MROWS, HKV * HD, DD, x, Wv, v);
    // attention: grid (N/128, H, B)
    attn_kernel<<<dim3(NN / ABR, HH, BB), ABR>>>(q, k, v, o);
    // out = o @ Wo
    sgemm128<<<dim3(DD / GBN, MROWS / GBM), 256>>>(MROWS, DD, DD, o, Wo, out);
}

// round 3
// speedup vs baseline: 3.2550x; 3.2550x over previous
#include <cuda_runtime.h>
#include <cuda_bf16.h>
#include <cstdint>

// Problem constants
#define BB 2
#define NN 2048
#define DD 1024
#define HH 16
#define HKV 4
#define HD 64
#define REP 4
#define MROWS (BB * NN)   // 4096
#define KVD (HKV * HD)    // 256

// ---------------------------------------------------------------------------
// Scratch (static device globals — allocation-free per harness rules)
// ---------------------------------------------------------------------------
__device__ float g_q[MROWS * DD];        // Q proj (rounded to tf32)
__device__ float g_k[MROWS * KVD];       // K proj (rounded)
__device__ float g_v[MROWS * KVD];       // V proj (rounded)
__device__ float g_o[MROWS * DD];        // attention out (rounded)
// tf32-rounded copies of the inputs
__device__ float g_x[MROWS * DD];
__device__ float g_wq[DD * DD];
__device__ float g_wk[DD * KVD];
__device__ float g_wv[DD * KVD];
__device__ float g_wo[DD * DD];

// ---------------------------------------------------------------------------
// Small helpers
// ---------------------------------------------------------------------------
__device__ __forceinline__ uint32_t f2tf32(float x) {
    uint32_t r;
    asm("cvt.rna.tf32.f32 %0, %1;" : "=r"(r) : "f"(x));
    return r;
}
__device__ __forceinline__ float ex2(float x) {
    float r;
    asm("ex2.approx.ftz.f32 %0, %1;" : "=f"(r) : "f"(x));
    return r;
}
// D += A(16x8,row) * B(8x8,col)   tf32 -> f32
__device__ __forceinline__ void mma_tf32(float* c, const uint32_t* a,
                                         uint32_t b0, uint32_t b1) {
    asm volatile(
        "mma.sync.aligned.m16n8k8.row.col.f32.tf32.tf32.f32 "
        "{%0,%1,%2,%3}, {%4,%5,%6,%7}, {%8,%9}, {%0,%1,%2,%3};\n"
        : "+f"(c[0]), "+f"(c[1]), "+f"(c[2]), "+f"(c[3])
        : "r"(a[0]), "r"(a[1]), "r"(a[2]), "r"(a[3]), "r"(b0), "r"(b1));
}

// ---------------------------------------------------------------------------
// Input rounding: fp32 -> nearest tf32 (kept in fp32 storage)
// ---------------------------------------------------------------------------
__global__ void round_tf32_kernel(const float* __restrict__ in,
                                  float* __restrict__ out, int n4) {
    int i = blockIdx.x * blockDim.x + threadIdx.x;
    if (i < n4) {
        float4 v = ((const float4*)in)[i];
        v.x = __uint_as_float(f2tf32(v.x));
        v.y = __uint_as_float(f2tf32(v.y));
        v.z = __uint_as_float(f2tf32(v.z));
        v.w = __uint_as_float(f2tf32(v.w));
        ((float4*)out)[i] = v;
    }
}

// ---------------------------------------------------------------------------
// tf32 tensor-core GEMM: C[M,N] = A[M,K] @ B[K,N], row-major.
// 128x128 block tile, K-step 16, 8 warps (4 m-warps x 2 n-warps),
// warp tile 32x64 via m16n8k8. Padded smem strides => conflict-free LDS.
// ROUND_OUT: round result to nearest tf32 (for Q/K/V intermediates).
// ---------------------------------------------------------------------------
#define GK 16
#define GAS 136   // As_t[k][m] stride: 136 % 32 == 8
#define GBS 136   // Bs[k][n]   stride

template <bool ROUND_OUT>
__global__ __launch_bounds__(256, 2) void gemm_tf32(
    int M, int N, int K,
    const float* __restrict__ A, const float* __restrict__ B,
    float* __restrict__ C)
{
    __shared__ float As[GK][GAS];   // transposed: [k][m]
    __shared__ float Bs[GK][GBS];   // [k][n]

    const int tid  = threadIdx.x;
    const int lane = tid & 31;
    const int w    = tid >> 5;
    const int g    = lane >> 2;   // groupID 0..7
    const int t    = lane & 3;    // threadID_in_group 0..3
    const int wm   = (w & 3) * 32;
    const int wn   = (w >> 2) * 64;
    const int bm   = blockIdx.y * 128;
    const int bn   = blockIdx.x * 128;

    float acc[2][8][4];
#pragma unroll
    for (int mt = 0; mt < 2; mt++)
#pragma unroll
        for (int nt = 0; nt < 8; nt++)
#pragma unroll
            for (int j = 0; j < 4; j++) acc[mt][nt][j] = 0.f;

    for (int k0 = 0; k0 < K; k0 += GK) {
        // A tile: 128 rows x 16 k -> transposed into As[k][m]
#pragma unroll
        for (int i = 0; i < 2; i++) {
            int idx = tid + i * 256;
            int r   = idx >> 2;
            int c4  = (idx & 3) * 4;
            float4 v = *(const float4*)(A + (size_t)(bm + r) * K + k0 + c4);
            As[c4 + 0][r] = v.x;
            As[c4 + 1][r] = v.y;
            As[c4 + 2][r] = v.z;
            As[c4 + 3][r] = v.w;
        }
        // B tile: 16 k-rows x 128 n
#pragma unroll
        for (int i = 0; i < 2; i++) {
            int idx = tid + i * 256;
            int r   = idx >> 5;
            int c4  = (idx & 31) * 4;
            *(float4*)&Bs[r][c4] =
                *(const float4*)(B + (size_t)(k0 + r) * N + bn + c4);
        }
        __syncthreads();

#pragma unroll
        for (int kk = 0; kk < GK; kk += 8) {
            uint32_t a[2][4];
#pragma unroll
            for (int mt = 0; mt < 2; mt++) {
                int m = wm + mt * 16;
                a[mt][0] = __float_as_uint(As[kk + t][m + g]);
                a[mt][1] = __float_as_uint(As[kk + t][m + g + 8]);
                a[mt][2] = __float_as_uint(As[kk + t + 4][m + g]);
                a[mt][3] = __float_as_uint(As[kk + t + 4][m + g + 8]);
            }
#pragma unroll
            for (int nt = 0; nt < 8; nt++) {
                int n = wn + nt * 8 + g;
                uint32_t b0 = __float_as_uint(Bs[kk + t][n]);
                uint32_t b1 = __float_as_uint(Bs[kk + t + 4][n]);
                mma_tf32(acc[0][nt], a[0], b0, b1);
                mma_tf32(acc[1][nt], a[1], b0, b1);
            }
        }
        __syncthreads();
    }

#pragma unroll
    for (int mt = 0; mt < 2; mt++)
#pragma unroll
        for (int nt = 0; nt < 8; nt++) {
            int row = bm + wm + mt * 16 + g;
            int col = bn + wn + nt * 8 + 2 * t;
            float v0 = acc[mt][nt][0], v1 = acc[mt][nt][1];
            float v2 = acc[mt][nt][2], v3 = acc[mt][nt][3];
            if (ROUND_OUT) {
                v0 = __uint_as_float(f2tf32(v0));
                v1 = __uint_as_float(f2tf32(v1));
                v2 = __uint_as_float(f2tf32(v2));
                v3 = __uint_as_float(f2tf32(v3));
            }
            *(float2*)(C + (size_t)row * N + col) = make_float2(v0, v1);
            *(float2*)(C + (size_t)(row + 8) * N + col) = make_float2(v2, v3);
        }
}

// ---------------------------------------------------------------------------
// Tensor-core flash attention (tf32). Br=64 (4 warps x 16 rows), Bc=64.
// Per warp: S(16x64) = Qfrag @ K^T, online softmax on fragments,
// P staged in per-warp smem (rounded to tf32), O += P @ V.
// ---------------------------------------------------------------------------
#define KS_STRIDE 68   // 68 % 32 == 4 -> conflict-free S B-frag loads
#define VS_STRIDE 72   // 72 % 32 == 8 -> conflict-free PV B-frag loads
#define PS_STRIDE 72   // conflict-free for both P stores and A-frag loads
#define ATT_SMEM ((64 * KS_STRIDE + 64 * VS_STRIDE + 64 * PS_STRIDE) * 4)

__global__ __launch_bounds__(128, 3) void attn_tc(
    const float* __restrict__ Q, const float* __restrict__ K,
    const float* __restrict__ V, float* __restrict__ O)
{
    extern __shared__ float sm[];
    float* Ks = sm;
    float* Vs = sm + 64 * KS_STRIDE;
    float* Ps = sm + 64 * KS_STRIDE + 64 * VS_STRIDE;

    const int tid  = threadIdx.x;
    const int lane = tid & 31;
    const int w    = tid >> 5;
    const int g    = lane >> 2;
    const int t    = lane & 3;
    const int b    = blockIdx.z;
    const int h    = blockIdx.y;
    const int q0   = blockIdx.x * 64;
    const int kvh  = h >> 2;  // h / REP
    const float SCALE = 0.125f * 1.4426950408889634f;  // 1/sqrt(64) * log2(e)

    // Q fragments for this warp's 16 rows (held in registers whole kernel)
    uint32_t qa[8][4];
    {
        const float* qb = Q + (size_t)(b * NN + q0 + w * 16) * DD + h * HD;
#pragma unroll
        for (int kf = 0; kf < 8; kf++) {
            qa[kf][0] = f2tf32(qb[(size_t)g * DD + kf * 8 + t] * SCALE);
            qa[kf][1] = f2tf32(qb[(size_t)(g + 8) * DD + kf * 8 + t] * SCALE);
            qa[kf][2] = f2tf32(qb[(size_t)g * DD + kf * 8 + t + 4] * SCALE);
            qa[kf][3] = f2tf32(qb[(size_t)(g + 8) * DD + kf * 8 + t + 4] * SCALE);
        }
    }

    float o[8][4];
#pragma unroll
    for (int nt = 0; nt < 8; nt++)
#pragma unroll
        for (int j = 0; j < 4; j++) o[nt][j] = 0.f;
    float m0 = -1e30f, m1 = -1e30f, l0 = 0.f, l1 = 0.f;

    for (int kt = 0; kt < NN / 64; kt++) {
        __syncthreads();
        {
            const float* kb = K + (size_t)(b * NN + kt * 64) * KVD + kvh * HD;
            const float* vb = V + (size_t)(b * NN + kt * 64) * KVD + kvh * HD;
#pragma unroll
            for (int i = 0; i < 8; i++) {
                int idx = tid + i * 128;
                int r   = idx >> 4;
                int c4  = (idx & 15) * 4;
                *(float4*)&Ks[r * KS_STRIDE + c4] =
                    *(const float4*)(kb + (size_t)r * KVD + c4);
                *(float4*)&Vs[r * VS_STRIDE + c4] =
                    *(const float4*)(vb + (size_t)r * KVD + c4);
            }
        }
        __syncthreads();

        // S = Q @ K^T  (16 x 64)
        float s[8][4];
#pragma unroll
        for (int nt = 0; nt < 8; nt++)
#pragma unroll
            for (int j = 0; j < 4; j++) s[nt][j] = 0.f;
#pragma unroll
        for (int kf = 0; kf < 8; kf++) {
#pragma unroll
            for (int nt = 0; nt < 8; nt++) {
                const float* kr = &Ks[(nt * 8 + g) * KS_STRIDE + kf * 8 + t];
                uint32_t b0 = __float_as_uint(kr[0]);
                uint32_t b1 = __float_as_uint(kr[4]);
                mma_tf32(s[nt], qa[kf], b0, b1);
            }
        }

        // online softmax (rows g and g+8)
        float mx0 = -1e30f, mx1 = -1e30f;
#pragma unroll
        for (int nt = 0; nt < 8; nt++) {
            mx0 = fmaxf(mx0, fmaxf(s[nt][0], s[nt][1]));
            mx1 = fmaxf(mx1, fmaxf(s[nt][2], s[nt][3]));
        }
        mx0 = fmaxf(mx0, __shfl_xor_sync(0xffffffffu, mx0, 1));
        mx0 = fmaxf(mx0, __shfl_xor_sync(0xffffffffu, mx0, 2));
        mx1 = fmaxf(mx1, __shfl_xor_sync(0xffffffffu, mx1, 1));
        mx1 = fmaxf(mx1, __shfl_xor_sync(0xffffffffu, mx1, 2));
        const float nm0 = fmaxf(m0, mx0), nm1 = fmaxf(m1, mx1);
        const float cf0 = ex2(m0 - nm0), cf1 = ex2(m1 - nm1);
        m0 = nm0; m1 = nm1;
        l0 *= cf0; l1 *= cf1;
#pragma unroll
        for (int nt = 0; nt < 8; nt++) {
            o[nt][0] *= cf0; o[nt][1] *= cf0;
            o[nt][2] *= cf1; o[nt][3] *= cf1;
        }
        // P = exp2(S - m), accumulate lane-partial row sums, stage to smem
#pragma unroll
        for (int nt = 0; nt < 8; nt++) {
            float p0 = ex2(s[nt][0] - m0), p1 = ex2(s[nt][1] - m0);
            float p2 = ex2(s[nt][2] - m1), p3 = ex2(s[nt][3] - m1);
            l0 += p0 + p1;
            l1 += p2 + p3;
            uint2 u01 = make_uint2(f2tf32(p0), f2tf32(p1));
            uint2 u23 = make_uint2(f2tf32(p2), f2tf32(p3));
            *(uint2*)&Ps[(w * 16 + g) * PS_STRIDE + nt * 8 + 2 * t] = u01;
            *(uint2*)&Ps[(w * 16 + g + 8) * PS_STRIDE + nt * 8 + 2 * t] = u23;
        }
        __syncwarp();

        // O += P @ V
#pragma unroll
        for (int kf = 0; kf < 8; kf++) {
            uint32_t a[4];
            a[0] = __float_as_uint(Ps[(w * 16 + g) * PS_STRIDE + kf * 8 + t]);
            a[1] = __float_as_uint(Ps[(w * 16 + g + 8) * PS_STRIDE + kf * 8 + t]);
            a[2] = __float_as_uint(Ps[(w * 16 + g) * PS_STRIDE + kf * 8 + t + 4]);
            a[3] = __float_as_uint(Ps[(w * 16 + g + 8) * PS_STRIDE + kf * 8 + t + 4]);
#pragma unroll
            for (int nt = 0; nt < 8; nt++) {
                uint32_t b0 = __float_as_uint(Vs[(kf * 8 + t) * VS_STRIDE + nt * 8 + g]);
                uint32_t b1 = __float_as_uint(Vs[(kf * 8 + t + 4) * VS_STRIDE + nt * 8 + g]);
                mma_tf32(o[nt], a, b0, b1);
            }
        }
    }

    // finalize: sum l across the 4 lanes sharing each row, normalize, store
    l0 += __shfl_xor_sync(0xffffffffu, l0, 1);
    l0 += __shfl_xor_sync(0xffffffffu, l0, 2);
    l1 += __shfl_xor_sync(0xffffffffu, l1, 1);
    l1 += __shfl_xor_sync(0xffffffffu, l1, 2);
    const float inv0 = 1.f / l0, inv1 = 1.f / l1;

    float* ob = O + (size_t)(b * NN + q0 + w * 16) * DD + h * HD;
#pragma unroll
    for (int nt = 0; nt < 8; nt++) {
        int col = nt * 8 + 2 * t;
        float v0 = __uint_as_float(f2tf32(o[nt][0] * inv0));
        float v1 = __uint_as_float(f2tf32(o[nt][1] * inv0));
        float v2 = __uint_as_float(f2tf32(o[nt][2] * inv1));
        float v3 = __uint_as_float(f2tf32(o[nt][3] * inv1));
        *(float2*)(ob + (size_t)g * DD + col) = make_float2(v0, v1);
        *(float2*)(ob + (size_t)(g + 8) * DD + col) = make_float2(v2, v3);
    }
}

// ---------------------------------------------------------------------------
// Launch
// ---------------------------------------------------------------------------
extern "C" void kernel_launch(void* const* d_in, const int* in_sizes, int n_in,
                              void* d_out, int out_size)
{
    const float* x  = (const float*)d_in[0];
    const float* Wq = (const float*)d_in[1];
    const float* Wk = (const float*)d_in[2];
    const float* Wv = (const float*)d_in[3];
    const float* Wo = (const float*)d_in[4];
    float* out = (float*)d_out;

    float *q, *k, *v, *o, *rx, *rwq, *rwk, *rwv, *rwo;
    cudaGetSymbolAddress((void**)&q,   g_q);
    cudaGetSymbolAddress((void**)&k,   g_k);
    cudaGetSymbolAddress((void**)&v,   g_v);
    cudaGetSymbolAddress((void**)&o,   g_o);
    cudaGetSymbolAddress((void**)&rx,  g_x);
    cudaGetSymbolAddress((void**)&rwq, g_wq);
    cudaGetSymbolAddress((void**)&rwk, g_wk);
    cudaGetSymbolAddress((void**)&rwv, g_wv);
    cudaGetSymbolAddress((void**)&rwo, g_wo);

    cudaFuncSetAttribute(attn_tc, cudaFuncAttributeMaxDynamicSharedMemorySize,
                         ATT_SMEM);

    // round inputs to nearest tf32
    auto rnd = [](const float* in, float* outp, int n) {
        int n4 = n / 4;
        round_tf32_kernel<<<(n4 + 255) / 256, 256>>>(in, outp, n4);
    };
    rnd(x,  rx,  MROWS * DD);
    rnd(Wq, rwq, DD * DD);
    rnd(Wk, rwk, DD * KVD);
    rnd(Wv, rwv, DD * KVD);
    rnd(Wo, rwo, DD * DD);

    // projections (round outputs: they feed tf32 MMAs)
    gemm_tf32<true><<<dim3(DD / 128, MROWS / 128), 256>>>(MROWS, DD, DD, rx, rwq, q);
    gemm_tf32<true><<<dim3(KVD / 128, MROWS / 128), 256>>>(MROWS, KVD, DD, rx, rwk, k);
    gemm_tf32<true><<<dim3(KVD / 128, MROWS / 128), 256>>>(MROWS, KVD, DD, rx, rwv, v);

    // attention
    attn_tc<<<dim3(NN / 64, HH, BB), 128, ATT_SMEM>>>(q, k, v, o);

    // output projection (no rounding — final result)
    gemm_tf32<false><<<dim3(DD / 128, MROWS / 128), 256>>>(MROWS, DD, DD, o, rwo, out);
}

// round 4
// speedup vs baseline: 3.5764x; 1.0987x over previous
#include <cuda_runtime.h>
#include <cuda_bf16.h>
#include <cstdint>

// Problem constants
#define BB 2
#define NN 2048
#define DD 1024
#define HH 16
#define HKV 4
#define HD 64
#define REP 4
#define MROWS (BB * NN)   // 4096
#define KVD (HKV * HD)    // 256
#define QKVD (DD + 2 * KVD)  // 1536 packed q|k|v width

// ---------------------------------------------------------------------------
// Scratch (static device globals — allocation-free per harness rules)
// ---------------------------------------------------------------------------
__device__ float g_qkv[MROWS * QKVD];    // packed QKV projections (tf32-rounded)
__device__ float g_o[MROWS * DD];        // attention out (tf32-rounded)
__device__ float g_wqkv[DD * QKVD];      // packed Wq|Wk|Wv (tf32-rounded)

// ---------------------------------------------------------------------------
// Helpers
// ---------------------------------------------------------------------------
__device__ __forceinline__ uint32_t f2tf32(float x) {
    uint32_t r;
    asm("cvt.rna.tf32.f32 %0, %1;" : "=r"(r) : "f"(x));
    return r;
}
__device__ __forceinline__ float rnd_tf32(float x) {
    return __uint_as_float(f2tf32(x));
}
__device__ __forceinline__ float ex2(float x) {
    float r;
    asm("ex2.approx.ftz.f32 %0, %1;" : "=f"(r) : "f"(x));
    return r;
}
// D += A(16x8,row) * B(8x8,col)   tf32 -> f32
__device__ __forceinline__ void mma_tf32(float* c, const uint32_t* a,
                                         uint32_t b0, uint32_t b1) {
    asm volatile(
        "mma.sync.aligned.m16n8k8.row.col.f32.tf32.tf32.f32 "
        "{%0,%1,%2,%3}, {%4,%5,%6,%7}, {%8,%9}, {%0,%1,%2,%3};\n"
        : "+f"(c[0]), "+f"(c[1]), "+f"(c[2]), "+f"(c[3])
        : "r"(a[0]), "r"(a[1]), "r"(a[2]), "r"(a[3]), "r"(b0), "r"(b1));
}
// cp.async 16B
__device__ __forceinline__ void cp16(uint32_t dst, const void* src) {
    asm volatile("cp.async.ca.shared.global [%0], [%1], 16;"
                 :: "r"(dst), "l"(src));
}
#define CP_COMMIT() asm volatile("cp.async.commit_group;")
#define CP_WAIT(n)  asm volatile("cp.async.wait_group %0;" :: "n"(n))

// ---------------------------------------------------------------------------
// Pack Wq|Wk|Wv into [DD][QKVD], rounded to nearest tf32
// ---------------------------------------------------------------------------
__global__ void pack_w_kernel(const float* __restrict__ Wq,
                              const float* __restrict__ Wk,
                              const float* __restrict__ Wv,
                              float* __restrict__ out) {
    int i = blockIdx.x * blockDim.x + threadIdx.x;     // over DD*QKVD/4
    if (i >= DD * QKVD / 4) return;
    int row = i / (QKVD / 4);
    int c4  = (i % (QKVD / 4)) * 4;
    const float* src;
    if (c4 < DD)            src = Wq + (size_t)row * DD + c4;
    else if (c4 < DD + KVD) src = Wk + (size_t)row * KVD + (c4 - DD);
    else                    src = Wv + (size_t)row * KVD + (c4 - DD - KVD);
    float4 v = *(const float4*)src;
    v.x = rnd_tf32(v.x); v.y = rnd_tf32(v.y);
    v.z = rnd_tf32(v.z); v.w = rnd_tf32(v.w);
    *(float4*)(out + (size_t)row * QKVD + c4) = v;
}

// ---------------------------------------------------------------------------
// tf32 tensor-core GEMM, double-buffered via register prefetch.
// C[M,N] = A[M,K] @ B[K,N], row-major. 128x128 tile, K-step 16, 8 warps.
// RA/RB: round operand to tf32 on smem store. RC: round output.
// ---------------------------------------------------------------------------
#define GK 16
#define GAS 136
#define GBS 136

template <bool RA, bool RB, bool RC>
__global__ __launch_bounds__(256, 2) void gemm_tf32(
    int M, int N, int K,
    const float* __restrict__ A, const float* __restrict__ B,
    float* __restrict__ C)
{
    __shared__ float As[GK][GAS];   // transposed: [k][m]
    __shared__ float Bs[GK][GBS];   // [k][n]

    const int tid  = threadIdx.x;
    const int lane = tid & 31;
    const int w    = tid >> 5;
    const int g    = lane >> 2;
    const int t    = lane & 3;
    const int wm   = (w & 3) * 32;
    const int wn   = (w >> 2) * 64;
    const int bm   = blockIdx.y * 128;
    const int bn   = blockIdx.x * 128;

    const int aRow[2]  = { tid >> 2, (tid + 256) >> 2 };
    const int aCol4    = (tid & 3) * 4;
    const int bRow[2]  = { tid >> 5, (tid + 256) >> 5 };
    const int bCol4    = (tid & 31) * 4;

    const float* Ab = A + (size_t)bm * K;
    const float* Bb = B + bn;

    float acc[2][8][4];
#pragma unroll
    for (int mt = 0; mt < 2; mt++)
#pragma unroll
        for (int nt = 0; nt < 8; nt++)
#pragma unroll
            for (int j = 0; j < 4; j++) acc[mt][nt][j] = 0.f;

    float4 ar[2], br[2];

    auto ldg = [&](int k0) {
#pragma unroll
        for (int i = 0; i < 2; i++)
            ar[i] = *(const float4*)(Ab + (size_t)aRow[i] * K + k0 + aCol4);
#pragma unroll
        for (int i = 0; i < 2; i++)
            br[i] = *(const float4*)(Bb + (size_t)(k0 + bRow[i]) * N + bCol4);
    };
    auto sts = [&]() {
#pragma unroll
        for (int i = 0; i < 2; i++) {
            float4 v = ar[i];
            if (RA) { v.x = rnd_tf32(v.x); v.y = rnd_tf32(v.y);
                      v.z = rnd_tf32(v.z); v.w = rnd_tf32(v.w); }
            As[aCol4 + 0][aRow[i]] = v.x;
            As[aCol4 + 1][aRow[i]] = v.y;
            As[aCol4 + 2][aRow[i]] = v.z;
            As[aCol4 + 3][aRow[i]] = v.w;
        }
#pragma unroll
        for (int i = 0; i < 2; i++) {
            float4 v = br[i];
            if (RB) { v.x = rnd_tf32(v.x); v.y = rnd_tf32(v.y);
                      v.z = rnd_tf32(v.z); v.w = rnd_tf32(v.w); }
            *(float4*)&Bs[bRow[i]][bCol4] = v;
        }
    };
    auto compute = [&]() {
#pragma unroll
        for (int kk = 0; kk < GK; kk += 8) {
            uint32_t a[2][4];
#pragma unroll
            for (int mt = 0; mt < 2; mt++) {
                int m = wm + mt * 16;
                a[mt][0] = __float_as_uint(As[kk + t][m + g]);
                a[mt][1] = __float_as_uint(As[kk + t][m + g + 8]);
                a[mt][2] = __float_as_uint(As[kk + t + 4][m + g]);
                a[mt][3] = __float_as_uint(As[kk + t + 4][m + g + 8]);
            }
#pragma unroll
            for (int nt = 0; nt < 8; nt++) {
                int n = wn + nt * 8 + g;
                uint32_t b0 = __float_as_uint(Bs[kk + t][n]);
                uint32_t b1 = __float_as_uint(Bs[kk + t + 4][n]);
                mma_tf32(acc[0][nt], a[0], b0, b1);
                mma_tf32(acc[1][nt], a[1], b0, b1);
            }
        }
    };

    // pipelined mainloop: global loads for tile k0+GK overlap compute of k0
    ldg(0);
    sts();
    __syncthreads();
    for (int k0 = GK; k0 < K; k0 += GK) {
        ldg(k0);
        compute();
        __syncthreads();
        sts();
        __syncthreads();
    }
    compute();

#pragma unroll
    for (int mt = 0; mt < 2; mt++)
#pragma unroll
        for (int nt = 0; nt < 8; nt++) {
            int row = bm + wm + mt * 16 + g;
            int col = bn + wn + nt * 8 + 2 * t;
            float v0 = acc[mt][nt][0], v1 = acc[mt][nt][1];
            float v2 = acc[mt][nt][2], v3 = acc[mt][nt][3];
            if (RC) {
                v0 = rnd_tf32(v0); v1 = rnd_tf32(v1);
                v2 = rnd_tf32(v2); v3 = rnd_tf32(v3);
            }
            *(float2*)(C + (size_t)row * N + col) = make_float2(v0, v1);
            *(float2*)(C + (size_t)(row + 8) * N + col) = make_float2(v2, v3);
        }
}

// ---------------------------------------------------------------------------
// Tensor-core flash attention (tf32), cp.async double-buffered K/V tiles.
// Br=64 (4 warps x 16 rows), Bc=64. Reads packed QKV.
// ---------------------------------------------------------------------------
#define KS_STRIDE 68
#define VS_STRIDE 72
#define PS_STRIDE 72
#define NT (NN / 64)
#define ATT_SMEM ((2 * 64 * KS_STRIDE + 2 * 64 * VS_STRIDE + 64 * PS_STRIDE) * 4)

__global__ __launch_bounds__(128, 2) void attn_tc(
    const float* __restrict__ QKV, float* __restrict__ O)
{
    extern __shared__ float sm[];
    float* KsS[2] = { sm, sm + 64 * KS_STRIDE };
    float* VsS[2] = { sm + 2 * 64 * KS_STRIDE,
                      sm + 2 * 64 * KS_STRIDE + 64 * VS_STRIDE };
    float* Ps = sm + 2 * 64 * KS_STRIDE + 2 * 64 * VS_STRIDE;

    const int tid  = threadIdx.x;
    const int lane = tid & 31;
    const int w    = tid >> 5;
    const int g    = lane >> 2;
    const int t    = lane & 3;
    const int b    = blockIdx.z;
    const int h    = blockIdx.y;
    const int q0   = blockIdx.x * 64;
    const int kvh  = h >> 2;
    const float SCALE = 0.125f * 1.4426950408889634f;

    const float* kbase = QKV + (size_t)b * NN * QKVD + DD + kvh * HD;
    const float* vbase = QKV + (size_t)b * NN * QKVD + DD + KVD + kvh * HD;

    // per-thread tile-load coords: 64 rows x 16 float4, 8 per thread
    const int lr  = tid >> 4;          // 0..7 base row
    const int lc4 = (tid & 15) * 4;    // float4 col

    auto issue_tile = [&](int stage, int kt) {
        uint32_t kdst = (uint32_t)__cvta_generic_to_shared(
                            KsS[stage] + lr * KS_STRIDE + lc4);
        uint32_t vdst = (uint32_t)__cvta_generic_to_shared(
                            VsS[stage] + lr * VS_STRIDE + lc4);
        const float* ksrc = kbase + (size_t)(kt * 64 + lr) * QKVD + lc4;
        const float* vsrc = vbase + (size_t)(kt * 64 + lr) * QKVD + lc4;
#pragma unroll
        for (int i = 0; i < 8; i++) {
            cp16(kdst + i * 8 * KS_STRIDE * 4, ksrc + (size_t)8 * i * QKVD);
            cp16(vdst + i * 8 * VS_STRIDE * 4, vsrc + (size_t)8 * i * QKVD);
        }
    };

    // Q fragments (registers, whole kernel)
    uint32_t qa[8][4];
    {
        const float* qb = QKV + (size_t)(b * NN + q0 + w * 16) * QKVD + h * HD;
#pragma unroll
        for (int kf = 0; kf < 8; kf++) {
            qa[kf][0] = f2tf32(qb[(size_t)g * QKVD + kf * 8 + t] * SCALE);
            qa[kf][1] = f2tf32(qb[(size_t)(g + 8) * QKVD + kf * 8 + t] * SCALE);
            qa[kf][2] = f2tf32(qb[(size_t)g * QKVD + kf * 8 + t + 4] * SCALE);
            qa[kf][3] = f2tf32(qb[(size_t)(g + 8) * QKVD + kf * 8 + t + 4] * SCALE);
        }
    }

    float o[8][4];
#pragma unroll
    for (int nt = 0; nt < 8; nt++)
#pragma unroll
        for (int j = 0; j < 4; j++) o[nt][j] = 0.f;
    float m0 = -1e30f, m1 = -1e30f, l0 = 0.f, l1 = 0.f;

    issue_tile(0, 0);
    CP_COMMIT();

    for (int kt = 0; kt < NT; kt++) {
        const int st = kt & 1;
        if (kt + 1 < NT) {
            issue_tile(st ^ 1, kt + 1);
            CP_COMMIT();
            CP_WAIT(1);
        } else {
            CP_WAIT(0);
        }
        __syncthreads();

        const float* Ks = KsS[st];
        const float* Vs = VsS[st];

        // S = Q @ K^T  (16 x 64)
        float s[8][4];
#pragma unroll
        for (int nt = 0; nt < 8; nt++)
#pragma unroll
            for (int j = 0; j < 4; j++) s[nt][j] = 0.f;
#pragma unroll
        for (int kf = 0; kf < 8; kf++) {
#pragma unroll
            for (int nt = 0; nt < 8; nt++) {
                const float* kr = &Ks[(nt * 8 + g) * KS_STRIDE + kf * 8 + t];
                uint32_t b0 = __float_as_uint(kr[0]);
                uint32_t b1 = __float_as_uint(kr[4]);
                mma_tf32(s[nt], qa[kf], b0, b1);
            }
        }

        // online softmax (rows g and g+8)
        float mx0 = -1e30f, mx1 = -1e30f;
#pragma unroll
        for (int nt = 0; nt < 8; nt++) {
            mx0 = fmaxf(mx0, fmaxf(s[nt][0], s[nt][1]));
            mx1 = fmaxf(mx1, fmaxf(s[nt][2], s[nt][3]));
        }
        mx0 = fmaxf(mx0, __shfl_xor_sync(0xffffffffu, mx0, 1));
        mx0 = fmaxf(mx0, __shfl_xor_sync(0xffffffffu, mx0, 2));
        mx1 = fmaxf(mx1, __shfl_xor_sync(0xffffffffu, mx1, 1));
        mx1 = fmaxf(mx1, __shfl_xor_sync(0xffffffffu, mx1, 2));
        const float nm0 = fmaxf(m0, mx0), nm1 = fmaxf(m1, mx1);
        const float cf0 = ex2(m0 - nm0), cf1 = ex2(m1 - nm1);
        m0 = nm0; m1 = nm1;
        l0 *= cf0; l1 *= cf1;
#pragma unroll
        for (int nt = 0; nt < 8; nt++) {
            o[nt][0] *= cf0; o[nt][1] *= cf0;
            o[nt][2] *= cf1; o[nt][3] *= cf1;
        }
#pragma unroll
        for (int nt = 0; nt < 8; nt++) {
            float p0 = ex2(s[nt][0] - m0), p1 = ex2(s[nt][1] - m0);
            float p2 = ex2(s[nt][2] - m1), p3 = ex2(s[nt][3] - m1);
            l0 += p0 + p1;
            l1 += p2 + p3;
            uint2 u01 = make_uint2(f2tf32(p0), f2tf32(p1));
            uint2 u23 = make_uint2(f2tf32(p2), f2tf32(p3));
            *(uint2*)&Ps[(w * 16 + g) * PS_STRIDE + nt * 8 + 2 * t] = u01;
            *(uint2*)&Ps[(w * 16 + g + 8) * PS_STRIDE + nt * 8 + 2 * t] = u23;
        }
        __syncwarp();

        // O += P @ V
#pragma unroll
        for (int kf = 0; kf < 8; kf++) {
            uint32_t a[4];
            a[0] = __float_as_uint(Ps[(w * 16 + g) * PS_STRIDE + kf * 8 + t]);
            a[1] = __float_as_uint(Ps[(w * 16 + g + 8) * PS_STRIDE + kf * 8 + t]);
            a[2] = __float_as_uint(Ps[(w * 16 + g) * PS_STRIDE + kf * 8 + t + 4]);
            a[3] = __float_as_uint(Ps[(w * 16 + g + 8) * PS_STRIDE + kf * 8 + t + 4]);
#pragma unroll
            for (int nt = 0; nt < 8; nt++) {
                uint32_t b0 = __float_as_uint(Vs[(kf * 8 + t) * VS_STRIDE + nt * 8 + g]);
                uint32_t b1 = __float_as_uint(Vs[(kf * 8 + t + 4) * VS_STRIDE + nt * 8 + g]);
                mma_tf32(o[nt], a, b0, b1);
            }
        }
        __syncthreads();   // all warps done with stage st before it is refilled
    }

    l0 += __shfl_xor_sync(0xffffffffu, l0, 1);
    l0 += __shfl_xor_sync(0xffffffffu, l0, 2);
    l1 += __shfl_xor_sync(0xffffffffu, l1, 1);
    l1 += __shfl_xor_sync(0xffffffffu, l1, 2);
    const float inv0 = 1.f / l0, inv1 = 1.f / l1;

    float* ob = O + (size_t)(b * NN + q0 + w * 16) * DD + h * HD;
#pragma unroll
    for (int nt = 0; nt < 8; nt++) {
        int col = nt * 8 + 2 * t;
        float v0 = rnd_tf32(o[nt][0] * inv0);
        float v1 = rnd_tf32(o[nt][1] * inv0);
        float v2 = rnd_tf32(o[nt][2] * inv1);
        float v3 = rnd_tf32(o[nt][3] * inv1);
        *(float2*)(ob + (size_t)g * DD + col) = make_float2(v0, v1);
        *(float2*)(ob + (size_t)(g + 8) * DD + col) = make_float2(v2, v3);
    }
}

// ---------------------------------------------------------------------------
// Launch
// ---------------------------------------------------------------------------
extern "C" void kernel_launch(void* const* d_in, const int* in_sizes, int n_in,
                              void* d_out, int out_size)
{
    const float* x  = (const float*)d_in[0];
    const float* Wq = (const float*)d_in[1];
    const float* Wk = (const float*)d_in[2];
    const float* Wv = (const float*)d_in[3];
    const float* Wo = (const float*)d_in[4];
    float* out = (float*)d_out;

    float *qkv, *o, *wqkv;
    cudaGetSymbolAddress((void**)&qkv,  g_qkv);
    cudaGetSymbolAddress((void**)&o,    g_o);
    cudaGetSymbolAddress((void**)&wqkv, g_wqkv);

    cudaFuncSetAttribute(attn_tc, cudaFuncAttributeMaxDynamicSharedMemorySize,
                         ATT_SMEM);

    // pack + round Wq|Wk|Wv
    {
        int n4 = DD * QKVD / 4;
        pack_w_kernel<<<(n4 + 255) / 256, 256>>>(Wq, Wk, Wv, wqkv);
    }

    // fused QKV projection: A=x (round on load), C rounded
    gemm_tf32<true, false, true>
        <<<dim3(QKVD / 128, MROWS / 128), 256>>>(MROWS, QKVD, DD, x, wqkv, qkv);

    // attention
    attn_tc<<<dim3(NN / 64, HH, BB), 128, ATT_SMEM>>>(qkv, o);

    // output projection: B=Wo (round on load), C unrounded
    gemm_tf32<false, true, false>
        <<<dim3(DD / 128, MROWS / 128), 256>>>(MROWS, DD, DD, o, Wo, out);
}